// round 2
// baseline (speedup 1.0000x reference)
#include <cuda_runtime.h>
#include <cstdint>

// ============================================================================
// out = adj @ (x @ W)
//   x   [16384, 2048] f32  (d_in[0])
//   adj [16384,16384] f32  (d_in[1])
//   W   [ 2048,  512] f32  (d_in[2])
//   out [16384,  512] f32
//
// Two invocations of one tf32 mma.sync GEMM kernel:
//   h   = x   @ W    (K=2048)
//   out = adj @ h    (K=16384)
// C[M,512] = A[M,K] (row-major) * B[K,512] (row-major).
// tcgen05 / TMA are unavailable: the harness's PTX stage targets compute_103
// (no 'a' suffix), which rejects all arch-specific instructions. mma.sync
// (HMMA) + cvt.rna.tf32 is portable PTX and runs on the tensor pipe.
// ============================================================================

#define BM 128
#define BN 128
#define BK 32
#define NTHREADS 256
#define NCOLS 512              // N is 512 for both GEMMs
#define SA 36                  // A smem row stride in floats (32 + 4 pad)
#define SB 132                 // B smem row stride in floats (128 + 4 pad)

static constexpr int A_STAGE = BM * SA;              // 4608 floats
static constexpr int B_STAGE = BK * SB;              // 4224 floats
static constexpr int SMEM_FLOATS = 2 * (A_STAGE + B_STAGE);
static constexpr int SMEM_BYTES  = SMEM_FLOATS * 4;  // 70656 B

// scratch for h (no cudaMalloc allowed)
__device__ float g_h[(size_t)16384 * NCOLS];         // 32 MB

// round-to-nearest-even tf32 (unbiased; plain bit-feed would truncate)
__device__ __forceinline__ uint32_t f2tf(float f) {
    uint32_t u;
    asm("cvt.rna.tf32.f32 %0, %1;" : "=r"(u) : "f"(f));
    return u;
}

__device__ __forceinline__ void mma_tf32(float* d,
                                         const uint32_t* a,
                                         const uint32_t* b) {
    asm volatile(
        "mma.sync.aligned.m16n8k8.row.col.f32.tf32.tf32.f32 "
        "{%0,%1,%2,%3}, {%4,%5,%6,%7}, {%8,%9}, {%0,%1,%2,%3};"
        : "+f"(d[0]), "+f"(d[1]), "+f"(d[2]), "+f"(d[3])
        : "r"(a[0]), "r"(a[1]), "r"(a[2]), "r"(a[3]),
          "r"(b[0]), "r"(b[1]));
}

__global__ void __launch_bounds__(NTHREADS, 1)
gemm_tf32_kernel(const float* __restrict__ A, const float* __restrict__ B,
                 float* __restrict__ C, int K) {
    extern __shared__ float smem[];
    float* As = smem;                    // [2][BM*SA]
    float* Bs = smem + 2 * A_STAGE;      // [2][BK*SB]

    const int tid  = threadIdx.x;
    const int wid  = tid >> 5;
    const int lane = tid & 31;
    const int q    = lane >> 2;          // 0..7
    const int t    = lane & 3;           // 0..3

    const int m0 = blockIdx.y * BM;
    const int n0 = blockIdx.x * BN;
    const int wm = (wid & 1) * 64;       // warp m-origin within CTA tile
    const int wn = (wid >> 1) * 32;      // warp n-origin within CTA tile

    float acc[4][4][4];
    #pragma unroll
    for (int i = 0; i < 4; ++i)
        #pragma unroll
        for (int j = 0; j < 4; ++j)
            #pragma unroll
            for (int r = 0; r < 4; ++r)
                acc[i][j][r] = 0.0f;

    // Per-thread staging slots (4 float4 each for A and B)
    //  A tile: 128 rows x 8 float4;  slot s: row = s>>3, c4 = s&7
    //  B tile:  32 rows x 32 float4; slot s: row = s>>5, c4 = s&31
    float4 ar[4], br[4];

    const int niter = K / BK;

    // ---- prologue LDG (k-block 0) ----
    #pragma unroll
    for (int i = 0; i < 4; ++i) {
        int s = tid + i * NTHREADS;
        ar[i] = *(const float4*)(A + (size_t)(m0 + (s >> 3)) * K + (s & 7) * 4);
        br[i] = *(const float4*)(B + (size_t)(s >> 5) * NCOLS + n0 + (s & 31) * 4);
    }

    for (int it = 0; it < niter; ++it) {
        const int cur = it & 1;
        float* Ac = As + cur * A_STAGE;
        float* Bc = Bs + cur * B_STAGE;

        // ---- STS prefetched tile (convert to tf32 once here) ----
        #pragma unroll
        for (int i = 0; i < 4; ++i) {
            int s = tid + i * NTHREADS;
            uint4 ua, ub;
            ua.x = f2tf(ar[i].x); ua.y = f2tf(ar[i].y);
            ua.z = f2tf(ar[i].z); ua.w = f2tf(ar[i].w);
            ub.x = f2tf(br[i].x); ub.y = f2tf(br[i].y);
            ub.z = f2tf(br[i].z); ub.w = f2tf(br[i].w);
            *(uint4*)(Ac + (s >> 3) * SA + (s & 7) * 4)  = ua;
            *(uint4*)(Bc + (s >> 5) * SB + (s & 31) * 4) = ub;
        }
        __syncthreads();

        // ---- LDG next k-block (overlaps compute) ----
        if (it + 1 < niter) {
            const size_t kb = (size_t)(it + 1) * BK;
            #pragma unroll
            for (int i = 0; i < 4; ++i) {
                int s = tid + i * NTHREADS;
                ar[i] = *(const float4*)(A + (size_t)(m0 + (s >> 3)) * K + kb + (s & 7) * 4);
                br[i] = *(const float4*)(B + (kb + (s >> 5)) * NCOLS + n0 + (s & 31) * 4);
            }
        }

        // ---- compute: 4 k8-steps over the 64x32 warp tile ----
        #pragma unroll
        for (int k8 = 0; k8 < 4; ++k8) {
            uint32_t af[4][4];
            #pragma unroll
            for (int mi = 0; mi < 4; ++mi) {
                const uint32_t* ab = (const uint32_t*)
                    (Ac + (wm + mi * 16 + q) * SA + k8 * 8 + t);
                af[mi][0] = ab[0];
                af[mi][1] = ab[8 * SA];
                af[mi][2] = ab[4];
                af[mi][3] = ab[8 * SA + 4];
            }
            uint32_t bf[4][2];
            #pragma unroll
            for (int ni = 0; ni < 4; ++ni) {
                const uint32_t* bb = (const uint32_t*)
                    (Bc + (k8 * 8 + t) * SB + wn + ni * 8 + q);
                bf[ni][0] = bb[0];
                bf[ni][1] = bb[4 * SB];
            }
            #pragma unroll
            for (int mi = 0; mi < 4; ++mi)
                #pragma unroll
                for (int ni = 0; ni < 4; ++ni)
                    mma_tf32(acc[mi][ni], af[mi], bf[ni]);
        }
        __syncthreads();
    }

    // ---- epilogue: row-major C, float2 stores ----
    #pragma unroll
    for (int mi = 0; mi < 4; ++mi) {
        #pragma unroll
        for (int ni = 0; ni < 4; ++ni) {
            const int m = m0 + wm + mi * 16 + q;
            const int n = n0 + wn + ni * 8 + 2 * t;
            float2 v0 = make_float2(acc[mi][ni][0], acc[mi][ni][1]);
            float2 v1 = make_float2(acc[mi][ni][2], acc[mi][ni][3]);
            *(float2*)(C + (size_t)m * NCOLS + n)       = v0;
            *(float2*)(C + (size_t)(m + 8) * NCOLS + n) = v1;
        }
    }
}

// ---------------------------------------------------------------------------
extern "C" void kernel_launch(void* const* d_in, const int* in_sizes, int n_in,
                              void* d_out, int out_size) {
    const float* x   = (const float*)d_in[0];   // [16384, 2048]
    const float* adj = (const float*)d_in[1];   // [16384, 16384]
    const float* W   = (const float*)d_in[2];   // [2048, 512]
    float* out = (float*)d_out;                 // [16384, 512]

    float* h;
    cudaGetSymbolAddress((void**)&h, g_h);

    cudaFuncSetAttribute(gemm_tf32_kernel,
                         cudaFuncAttributeMaxDynamicSharedMemorySize, SMEM_BYTES);

    // grid.x = n-tiles (fast dim) so concurrent CTAs share the A row-slab in L2
    dim3 grid(NCOLS / BN, 16384 / BM);   // (4, 128)

    // h = x @ W
    gemm_tf32_kernel<<<grid, NTHREADS, SMEM_BYTES>>>(x, W, h, 2048);
    // out = adj @ h
    gemm_tf32_kernel<<<grid, NTHREADS, SMEM_BYTES>>>(adj, h, out, 16384);
}

// round 3
// speedup vs baseline: 1.1838x; 1.1838x over previous
#include <cuda_runtime.h>
#include <cstdint>

// ============================================================================
// out = adj @ (x @ W)
//   x   [16384, 2048] f32  (d_in[0])
//   adj [16384,16384] f32  (d_in[1])
//   W   [ 2048,  512] f32  (d_in[2])
//   out [16384,  512] f32
//
// tf32 mma.sync GEMM, cp.async 3-stage pipeline, 2 CTAs/SM.
//   h   = x   @ W    (K=2048)
//   out = adj @ h    (K=16384)
// ============================================================================

#define BM 128
#define BN 128
#define BK 32
#define NTHREADS 256
#define NCOLS 512
#define SA 36                  // A smem row stride (floats): 32 + 4 pad, 16B-multiple
#define SB 132                 // B smem row stride (floats): 128 + 4 pad, 16B-multiple
#define NSTAGE 3

static constexpr int A_STAGE_F   = BM * SA;                 // 4608 floats
static constexpr int B_STAGE_F   = BK * SB;                 // 4224 floats
static constexpr int STAGE_F     = A_STAGE_F + B_STAGE_F;   // 8832 floats (35328 B)
static constexpr int SMEM_BYTES  = NSTAGE * STAGE_F * 4;    // 105984 B

__device__ float g_h[(size_t)16384 * NCOLS];                // 32 MB scratch

__device__ __forceinline__ uint32_t f2tf(float f) {
    uint32_t u;
    asm("cvt.rna.tf32.f32 %0, %1;" : "=r"(u) : "f"(f));
    return u;
}

__device__ __forceinline__ uint32_t smem_u32(const void* p) {
    uint32_t a;
    asm("{ .reg .u64 t; cvta.to.shared.u64 t, %1; cvt.u32.u64 %0, t; }"
        : "=r"(a) : "l"(p));
    return a;
}

__device__ __forceinline__ void cp_async16(uint32_t dst, const void* src) {
    asm volatile("cp.async.cg.shared.global [%0], [%1], 16;"
                 :: "r"(dst), "l"(src));
}
__device__ __forceinline__ void cp_commit() {
    asm volatile("cp.async.commit_group;");
}
template <int N>
__device__ __forceinline__ void cp_wait() {
    asm volatile("cp.async.wait_group %0;" :: "n"(N));
}

__device__ __forceinline__ void mma_tf32(float* d,
                                         const uint32_t* a,
                                         const uint32_t* b) {
    asm volatile(
        "mma.sync.aligned.m16n8k8.row.col.f32.tf32.tf32.f32 "
        "{%0,%1,%2,%3}, {%4,%5,%6,%7}, {%8,%9}, {%0,%1,%2,%3};"
        : "+f"(d[0]), "+f"(d[1]), "+f"(d[2]), "+f"(d[3])
        : "r"(a[0]), "r"(a[1]), "r"(a[2]), "r"(a[3]),
          "r"(b[0]), "r"(b[1]));
}

__global__ void __launch_bounds__(NTHREADS, 2)
gemm_tf32_kernel(const float* __restrict__ A, const float* __restrict__ B,
                 float* __restrict__ C, int K) {
    extern __shared__ float smem[];

    const int tid  = threadIdx.x;
    const int wid  = tid >> 5;
    const int lane = tid & 31;
    const int q    = lane >> 2;          // 0..7
    const int t    = lane & 3;           // 0..3

    const int m0 = blockIdx.y * BM;
    const int n0 = blockIdx.x * BN;
    const int wm = (wid & 1) * 64;
    const int wn = (wid >> 1) * 32;

    // ---- cp.async source/dest bases (4 x 16B per tile per thread) ----
    // A tile: 128 rows x 8 chunks; slot s = tid + i*256: row s>>3, chunk s&7
    // B tile:  32 rows x 32 chunks; slot s: row s>>5, chunk s&31
    const float* a_src = A + (size_t)(m0 + (tid >> 3)) * K + (tid & 7) * 4;
    const float* b_src = B + (size_t)(tid >> 5) * NCOLS + n0 + (tid & 31) * 4;
    const uint32_t smem_base = smem_u32(smem);
    const uint32_t a_dst = smem_base + ((tid >> 3) * SA + (tid & 7) * 4) * 4;
    const uint32_t b_dst = smem_base + (A_STAGE_F + (tid >> 5) * SB + (tid & 31) * 4) * 4;

    const int niter = K / BK;

    // issue one stage's loads: stage buffer sbuf (0..2), k-block kb
    auto issue = [&](int sbuf, int kb) {
        const uint32_t soff = (uint32_t)(sbuf * STAGE_F * 4);
        const float* as = a_src + (size_t)kb * BK;
        const float* bs = b_src + (size_t)kb * BK * NCOLS;
        #pragma unroll
        for (int i = 0; i < 4; ++i)
            cp_async16(a_dst + soff + i * (32 * SA * 4), as + (size_t)i * 32 * K);
        #pragma unroll
        for (int i = 0; i < 4; ++i)
            cp_async16(b_dst + soff + i * (8 * SB * 4), bs + (size_t)i * 8 * NCOLS);
    };

    float acc[4][4][4];
    #pragma unroll
    for (int i = 0; i < 4; ++i)
        #pragma unroll
        for (int j = 0; j < 4; ++j)
            #pragma unroll
            for (int r = 0; r < 4; ++r)
                acc[i][j][r] = 0.0f;

    // ---- prologue: stages 0 and 1 in flight ----
    issue(0, 0); cp_commit();
    issue(1, 1); cp_commit();

    // per-warp smem fragment read offsets (floats, within a stage)
    const int aoff = (wm + q) * SA + t;
    const int boff = A_STAGE_F + t * SB + wn + q;

    int buf = 0;                          // it % 3
    for (int it = 0; it < niter; ++it) {
        cp_wait<1>();                     // stage `it` resident
        __syncthreads();                  // data visible; buf (it-1)%3 free

        // issue stage it+2 into buffer (it+2)%3 == (it-1)%3
        if (it + 2 < niter) {
            int nb = buf + 2; if (nb >= NSTAGE) nb -= NSTAGE;
            issue(nb, it + 2);
        }
        cp_commit();                      // always commit (keeps group count uniform)

        const float* Sc = smem + buf * STAGE_F;

        #pragma unroll
        for (int k8 = 0; k8 < 4; ++k8) {
            uint32_t af[4][4];
            #pragma unroll
            for (int mi = 0; mi < 4; ++mi) {
                const float* ab = Sc + aoff + mi * (16 * SA) + k8 * 8;
                af[mi][0] = f2tf(ab[0]);
                af[mi][1] = f2tf(ab[8 * SA]);
                af[mi][2] = f2tf(ab[4]);
                af[mi][3] = f2tf(ab[8 * SA + 4]);
            }
            uint32_t bf[4][2];
            #pragma unroll
            for (int ni = 0; ni < 4; ++ni) {
                const float* bb = Sc + boff + k8 * (8 * SB) + ni * 8;
                bf[ni][0] = f2tf(bb[0]);
                bf[ni][1] = f2tf(bb[4 * SB]);
            }
            #pragma unroll
            for (int mi = 0; mi < 4; ++mi)
                #pragma unroll
                for (int ni = 0; ni < 4; ++ni)
                    mma_tf32(acc[mi][ni], af[mi], bf[ni]);
        }

        if (++buf >= NSTAGE) buf = 0;
    }

    // ---- epilogue: row-major C, float2 stores ----
    #pragma unroll
    for (int mi = 0; mi < 4; ++mi) {
        #pragma unroll
        for (int ni = 0; ni < 4; ++ni) {
            const int m = m0 + wm + mi * 16 + q;
            const int n = n0 + wn + ni * 8 + 2 * t;
            *(float2*)(C + (size_t)m * NCOLS + n) =
                make_float2(acc[mi][ni][0], acc[mi][ni][1]);
            *(float2*)(C + (size_t)(m + 8) * NCOLS + n) =
                make_float2(acc[mi][ni][2], acc[mi][ni][3]);
        }
    }
}

// ---------------------------------------------------------------------------
extern "C" void kernel_launch(void* const* d_in, const int* in_sizes, int n_in,
                              void* d_out, int out_size) {
    const float* x   = (const float*)d_in[0];   // [16384, 2048]
    const float* adj = (const float*)d_in[1];   // [16384, 16384]
    const float* W   = (const float*)d_in[2];   // [2048, 512]
    float* out = (float*)d_out;                 // [16384, 512]

    float* h;
    cudaGetSymbolAddress((void**)&h, g_h);

    cudaFuncSetAttribute(gemm_tf32_kernel,
                         cudaFuncAttributeMaxDynamicSharedMemorySize, SMEM_BYTES);

    dim3 grid(NCOLS / BN, 16384 / BM);   // (4, 128)

    gemm_tf32_kernel<<<grid, NTHREADS, SMEM_BYTES>>>(x, W, h, 2048);
    gemm_tf32_kernel<<<grid, NTHREADS, SMEM_BYTES>>>(adj, h, out, 16384);
}

// round 4
// speedup vs baseline: 1.2253x; 1.0350x over previous
#include <cuda_runtime.h>
#include <cstdint>

// ============================================================================
// out = adj @ (x @ W)
//   x   [16384, 2048] f32  (d_in[0])
//   adj [16384,16384] f32  (d_in[1])
//   W   [ 2048,  512] f32  (d_in[2])
//   out [16384,  512] f32
//
// tf32 mma.sync GEMM, cp.async 3-stage pipeline, ldmatrix.x4 A-fragments,
// 2 CTAs/SM. h is written tf32-pre-rounded by GEMM1 so GEMM2 skips B cvt.
// ============================================================================

#define BM 128
#define BN 128
#define BK 32
#define NTHREADS 256
#define NCOLS 512
#define SA 36                  // A smem row stride (floats): 32 + 4 pad
#define SB 132                 // B smem row stride (floats): 128 + 4 pad
#define NSTAGE 3

static constexpr int A_STAGE_F   = BM * SA;                 // 4608 floats
static constexpr int B_STAGE_F   = BK * SB;                 // 4224 floats
static constexpr int STAGE_F     = A_STAGE_F + B_STAGE_F;   // 8832 floats
static constexpr int SMEM_BYTES  = NSTAGE * STAGE_F * 4;    // 105984 B

__device__ float g_h[(size_t)16384 * NCOLS];                // 32 MB scratch

__device__ __forceinline__ uint32_t f2tf(float f) {
    uint32_t u;
    asm("cvt.rna.tf32.f32 %0, %1;" : "=r"(u) : "f"(f));
    return u;
}
__device__ __forceinline__ uint32_t f2tf_u(uint32_t x) {
    return f2tf(__uint_as_float(x));
}

__device__ __forceinline__ uint32_t smem_u32(const void* p) {
    uint32_t a;
    asm("{ .reg .u64 t; cvta.to.shared.u64 t, %1; cvt.u32.u64 %0, t; }"
        : "=r"(a) : "l"(p));
    return a;
}

__device__ __forceinline__ void cp_async16(uint32_t dst, const void* src) {
    asm volatile("cp.async.cg.shared.global [%0], [%1], 16;"
                 :: "r"(dst), "l"(src));
}
__device__ __forceinline__ void cp_commit() {
    asm volatile("cp.async.commit_group;");
}
template <int N>
__device__ __forceinline__ void cp_wait() {
    asm volatile("cp.async.wait_group %0;" :: "n"(N));
}

__device__ __forceinline__ void ldsm_x4(uint32_t* r, uint32_t addr) {
    asm volatile(
        "ldmatrix.sync.aligned.m8n8.x4.shared.b16 {%0,%1,%2,%3}, [%4];"
        : "=r"(r[0]), "=r"(r[1]), "=r"(r[2]), "=r"(r[3]) : "r"(addr));
}

__device__ __forceinline__ void mma_tf32(float* d,
                                         const uint32_t* a,
                                         const uint32_t* b) {
    asm volatile(
        "mma.sync.aligned.m16n8k8.row.col.f32.tf32.tf32.f32 "
        "{%0,%1,%2,%3}, {%4,%5,%6,%7}, {%8,%9}, {%0,%1,%2,%3};"
        : "+f"(d[0]), "+f"(d[1]), "+f"(d[2]), "+f"(d[3])
        : "r"(a[0]), "r"(a[1]), "r"(a[2]), "r"(a[3]),
          "r"(b[0]), "r"(b[1]));
}

// CVT_A / CVT_B: convert operand from fp32 at fragment load.
// ROUND_OUT: write C tf32-pre-rounded (for h, consumed raw by GEMM2).
template <bool CVT_A, bool CVT_B, bool ROUND_OUT>
__global__ void __launch_bounds__(NTHREADS, 2)
gemm_tf32_kernel(const float* __restrict__ A, const float* __restrict__ B,
                 float* __restrict__ C, int K) {
    extern __shared__ float smem[];

    const int tid  = threadIdx.x;
    const int wid  = tid >> 5;
    const int lane = tid & 31;
    const int q    = lane >> 2;          // 0..7
    const int t    = lane & 3;           // 0..3

    const int m0 = blockIdx.y * BM;
    const int n0 = blockIdx.x * BN;
    const int wm = (wid & 1) * 64;
    const int wn = (wid >> 1) * 32;

    // cp.async fill bases (A: 4x16B/thread; B: 4x16B/thread per stage)
    const float* a_src = A + (size_t)(m0 + (tid >> 3)) * K + (tid & 7) * 4;
    const float* b_src = B + (size_t)(tid >> 5) * NCOLS + n0 + (tid & 31) * 4;
    const uint32_t smem_base = smem_u32(smem);
    const uint32_t a_dst = smem_base + ((tid >> 3) * SA + (tid & 7) * 4) * 4;
    const uint32_t b_dst = smem_base + (A_STAGE_F + (tid >> 5) * SB + (tid & 31) * 4) * 4;

    const int niter = K / BK;

    auto issue = [&](int sbuf, int kb) {
        const uint32_t soff = (uint32_t)(sbuf * STAGE_F * 4);
        const float* as = a_src + (size_t)kb * BK;
        const float* bs = b_src + (size_t)kb * BK * NCOLS;
        #pragma unroll
        for (int i = 0; i < 4; ++i)
            cp_async16(a_dst + soff + i * (32 * SA * 4), as + (size_t)i * 32 * K);
        #pragma unroll
        for (int i = 0; i < 4; ++i)
            cp_async16(b_dst + soff + i * (8 * SB * 4), bs + (size_t)i * 8 * NCOLS);
    };

    float acc[4][4][4];
    #pragma unroll
    for (int i = 0; i < 4; ++i)
        #pragma unroll
        for (int j = 0; j < 4; ++j)
            #pragma unroll
            for (int r = 0; r < 4; ++r)
                acc[i][j][r] = 0.0f;

    issue(0, 0); cp_commit();
    issue(1, 1); cp_commit();

    // ldmatrix lane addressing within a stage (byte offset):
    //   row = wm + mi*16 + (lane & 15), col = k8*8 + (lane>>4)*4
    const uint32_t a_lds = smem_base +
        (((wm + (lane & 15)) * SA + (lane >> 4) * 4) * 4);
    // B scalar fragment base (floats within a stage)
    const int boff = A_STAGE_F + t * SB + wn + q;

    int buf = 0;
    for (int it = 0; it < niter; ++it) {
        cp_wait<1>();
        __syncthreads();

        if (it + 2 < niter) {
            int nb = buf + 2; if (nb >= NSTAGE) nb -= NSTAGE;
            issue(nb, it + 2);
        }
        cp_commit();

        const uint32_t a_stage = a_lds + (uint32_t)(buf * STAGE_F * 4);
        const float*   Bc      = smem + buf * STAGE_F;

        #pragma unroll
        for (int k8 = 0; k8 < 4; ++k8) {
            uint32_t af[4][4];
            #pragma unroll
            for (int mi = 0; mi < 4; ++mi) {
                ldsm_x4(af[mi], a_stage + (uint32_t)((mi * 16 * SA + k8 * 8) * 4));
                if (CVT_A) {
                    af[mi][0] = f2tf_u(af[mi][0]);
                    af[mi][1] = f2tf_u(af[mi][1]);
                    af[mi][2] = f2tf_u(af[mi][2]);
                    af[mi][3] = f2tf_u(af[mi][3]);
                }
            }
            uint32_t bf[4][2];
            #pragma unroll
            for (int ni = 0; ni < 4; ++ni) {
                const float* bb = Bc + boff + k8 * (8 * SB) + ni * 8;
                if (CVT_B) {
                    bf[ni][0] = f2tf(bb[0]);
                    bf[ni][1] = f2tf(bb[4 * SB]);
                } else {
                    bf[ni][0] = ((const uint32_t*)bb)[0];
                    bf[ni][1] = ((const uint32_t*)bb)[4 * SB];
                }
            }
            #pragma unroll
            for (int mi = 0; mi < 4; ++mi)
                #pragma unroll
                for (int ni = 0; ni < 4; ++ni)
                    mma_tf32(acc[mi][ni], af[mi], bf[ni]);
        }

        if (++buf >= NSTAGE) buf = 0;
    }

    // ---- epilogue ----
    #pragma unroll
    for (int mi = 0; mi < 4; ++mi) {
        #pragma unroll
        for (int ni = 0; ni < 4; ++ni) {
            const int m = m0 + wm + mi * 16 + q;
            const int n = n0 + wn + ni * 8 + 2 * t;
            float v0 = acc[mi][ni][0], v1 = acc[mi][ni][1];
            float v2 = acc[mi][ni][2], v3 = acc[mi][ni][3];
            if (ROUND_OUT) {
                v0 = __uint_as_float(f2tf(v0));
                v1 = __uint_as_float(f2tf(v1));
                v2 = __uint_as_float(f2tf(v2));
                v3 = __uint_as_float(f2tf(v3));
            }
            *(float2*)(C + (size_t)m * NCOLS + n)       = make_float2(v0, v1);
            *(float2*)(C + (size_t)(m + 8) * NCOLS + n) = make_float2(v2, v3);
        }
    }
}

// ---------------------------------------------------------------------------
extern "C" void kernel_launch(void* const* d_in, const int* in_sizes, int n_in,
                              void* d_out, int out_size) {
    const float* x   = (const float*)d_in[0];   // [16384, 2048]
    const float* adj = (const float*)d_in[1];   // [16384, 16384]
    const float* W   = (const float*)d_in[2];   // [2048, 512]
    float* out = (float*)d_out;                 // [16384, 512]

    float* h;
    cudaGetSymbolAddress((void**)&h, g_h);

    cudaFuncSetAttribute(gemm_tf32_kernel<true, true, true>,
                         cudaFuncAttributeMaxDynamicSharedMemorySize, SMEM_BYTES);
    cudaFuncSetAttribute(gemm_tf32_kernel<true, false, false>,
                         cudaFuncAttributeMaxDynamicSharedMemorySize, SMEM_BYTES);

    dim3 grid(NCOLS / BN, 16384 / BM);   // (4, 128)

    // h = round_tf32(x @ W)
    gemm_tf32_kernel<true, true, true><<<grid, NTHREADS, SMEM_BYTES>>>(
        x, W, h, 2048);
    // out = adj @ h   (h already tf32: no B cvt)
    gemm_tf32_kernel<true, false, false><<<grid, NTHREADS, SMEM_BYTES>>>(
        adj, h, out, 16384);
}

// round 5
// speedup vs baseline: 1.3452x; 1.0979x over previous
#include <cuda_runtime.h>
#include <cstdint>

// ============================================================================
// out = adj @ (x @ W)
//   x   [16384, 2048] f32  (d_in[0])
//   adj [16384,16384] f32  (d_in[1])
//   W   [ 2048,  512] f32  (d_in[2])
//   out [16384,  512] f32
//
// tf32 mma.sync GEMM, cp.async 3-stage pipeline, ldmatrix.x4 A-fragments,
// fragment double-buffering across k8-steps (hides LDS latency under MMAs),
// 2 CTAs/SM. h written tf32-pre-rounded by GEMM1 so GEMM2 skips B cvt.
// ============================================================================

#define BM 128
#define BN 128
#define BK 32
#define NTHREADS 256
#define NCOLS 512
#define SA 36                  // A smem row stride (floats): 32 + 4 pad
#define SB 132                 // B smem row stride (floats): 128 + 4 pad
#define NSTAGE 3

static constexpr int A_STAGE_F   = BM * SA;                 // 4608 floats
static constexpr int B_STAGE_F   = BK * SB;                 // 4224 floats
static constexpr int STAGE_F     = A_STAGE_F + B_STAGE_F;   // 8832 floats
static constexpr int SMEM_BYTES  = NSTAGE * STAGE_F * 4;    // 105984 B

__device__ float g_h[(size_t)16384 * NCOLS];                // 32 MB scratch

__device__ __forceinline__ uint32_t f2tf(float f) {
    uint32_t u;
    asm("cvt.rna.tf32.f32 %0, %1;" : "=r"(u) : "f"(f));
    return u;
}
__device__ __forceinline__ uint32_t f2tf_u(uint32_t x) {
    return f2tf(__uint_as_float(x));
}

__device__ __forceinline__ uint32_t smem_u32(const void* p) {
    uint32_t a;
    asm("{ .reg .u64 t; cvta.to.shared.u64 t, %1; cvt.u32.u64 %0, t; }"
        : "=r"(a) : "l"(p));
    return a;
}

__device__ __forceinline__ void cp_async16(uint32_t dst, const void* src) {
    asm volatile("cp.async.cg.shared.global [%0], [%1], 16;"
                 :: "r"(dst), "l"(src));
}
__device__ __forceinline__ void cp_commit() {
    asm volatile("cp.async.commit_group;");
}
template <int N>
__device__ __forceinline__ void cp_wait() {
    asm volatile("cp.async.wait_group %0;" :: "n"(N));
}

__device__ __forceinline__ void ldsm_x4(uint32_t* r, uint32_t addr) {
    asm volatile(
        "ldmatrix.sync.aligned.m8n8.x4.shared.b16 {%0,%1,%2,%3}, [%4];"
        : "=r"(r[0]), "=r"(r[1]), "=r"(r[2]), "=r"(r[3]) : "r"(addr));
}

__device__ __forceinline__ void mma_tf32(float* d,
                                         const uint32_t* a,
                                         const uint32_t* b) {
    asm volatile(
        "mma.sync.aligned.m16n8k8.row.col.f32.tf32.tf32.f32 "
        "{%0,%1,%2,%3}, {%4,%5,%6,%7}, {%8,%9}, {%0,%1,%2,%3};"
        : "+f"(d[0]), "+f"(d[1]), "+f"(d[2]), "+f"(d[3])
        : "r"(a[0]), "r"(a[1]), "r"(a[2]), "r"(a[3]),
          "r"(b[0]), "r"(b[1]));
}

template <bool CVT_A, bool CVT_B, bool ROUND_OUT>
__global__ void __launch_bounds__(NTHREADS, 2)
gemm_tf32_kernel(const float* __restrict__ A, const float* __restrict__ B,
                 float* __restrict__ C, int K) {
    extern __shared__ float smem[];

    const int tid  = threadIdx.x;
    const int wid  = tid >> 5;
    const int lane = tid & 31;
    const int q    = lane >> 2;          // 0..7
    const int t    = lane & 3;           // 0..3

    const int m0 = blockIdx.y * BM;
    const int n0 = blockIdx.x * BN;
    const int wm = (wid & 1) * 64;
    const int wn = (wid >> 1) * 32;

    const float* a_src = A + (size_t)(m0 + (tid >> 3)) * K + (tid & 7) * 4;
    const float* b_src = B + (size_t)(tid >> 5) * NCOLS + n0 + (tid & 31) * 4;
    const uint32_t smem_base = smem_u32(smem);
    const uint32_t a_dst = smem_base + ((tid >> 3) * SA + (tid & 7) * 4) * 4;
    const uint32_t b_dst = smem_base + (A_STAGE_F + (tid >> 5) * SB + (tid & 31) * 4) * 4;

    const int niter = K / BK;

    auto issue = [&](int sbuf, int kb) {
        const uint32_t soff = (uint32_t)(sbuf * STAGE_F * 4);
        const float* as = a_src + (size_t)kb * BK;
        const float* bs = b_src + (size_t)kb * BK * NCOLS;
        #pragma unroll
        for (int i = 0; i < 4; ++i)
            cp_async16(a_dst + soff + i * (32 * SA * 4), as + (size_t)i * 32 * K);
        #pragma unroll
        for (int i = 0; i < 4; ++i)
            cp_async16(b_dst + soff + i * (8 * SB * 4), bs + (size_t)i * 8 * NCOLS);
    };

    float acc[4][4][4];
    #pragma unroll
    for (int i = 0; i < 4; ++i)
        #pragma unroll
        for (int j = 0; j < 4; ++j)
            #pragma unroll
            for (int r = 0; r < 4; ++r)
                acc[i][j][r] = 0.0f;

    issue(0, 0); cp_commit();
    issue(1, 1); cp_commit();

    // ldmatrix lane addressing (byte offsets within a stage):
    //   row = wm + mi*16 + (lane & 15), col4 = (lane>>4)*4, +k8*8 floats
    const uint32_t a_lds = smem_base +
        (((wm + (lane & 15)) * SA + (lane >> 4) * 4) * 4);
    const int boff = A_STAGE_F + t * SB + wn + q;

    // double-buffered fragments
    uint32_t af[2][4][4];
    uint32_t bf[2][4][2];

    int buf = 0;
    for (int it = 0; it < niter; ++it) {
        cp_wait<1>();
        __syncthreads();

        const uint32_t a_stage = a_lds + (uint32_t)(buf * STAGE_F * 4);
        const float*   Bc      = smem + buf * STAGE_F;

        // fragment load for k8-step `k` into pipeline slot `pb`
        auto load_frags = [&](int k, int pb) {
            #pragma unroll
            for (int mi = 0; mi < 4; ++mi) {
                ldsm_x4(af[pb][mi], a_stage + (uint32_t)((mi * 16 * SA + k * 8) * 4));
                if (CVT_A) {
                    af[pb][mi][0] = f2tf_u(af[pb][mi][0]);
                    af[pb][mi][1] = f2tf_u(af[pb][mi][1]);
                    af[pb][mi][2] = f2tf_u(af[pb][mi][2]);
                    af[pb][mi][3] = f2tf_u(af[pb][mi][3]);
                }
            }
            #pragma unroll
            for (int ni = 0; ni < 4; ++ni) {
                const float* bb = Bc + boff + k * (8 * SB) + ni * 8;
                if (CVT_B) {
                    bf[pb][ni][0] = f2tf(bb[0]);
                    bf[pb][ni][1] = f2tf(bb[4 * SB]);
                } else {
                    bf[pb][ni][0] = ((const uint32_t*)bb)[0];
                    bf[pb][ni][1] = ((const uint32_t*)bb)[4 * SB];
                }
            }
        };

        load_frags(0, 0);

        // next stage's global loads: fire-and-forget, fills the pipe front
        if (it + 2 < niter) {
            int nb = buf + 2; if (nb >= NSTAGE) nb -= NSTAGE;
            issue(nb, it + 2);
        }
        cp_commit();

        #pragma unroll
        for (int k8 = 0; k8 < 4; ++k8) {
            const int cur = k8 & 1;
            if (k8 < 3) load_frags(k8 + 1, cur ^ 1);
            #pragma unroll
            for (int mi = 0; mi < 4; ++mi)
                #pragma unroll
                for (int ni = 0; ni < 4; ++ni)
                    mma_tf32(acc[mi][ni], af[cur][mi], bf[cur][ni]);
        }

        if (++buf >= NSTAGE) buf = 0;
    }

    // ---- epilogue ----
    #pragma unroll
    for (int mi = 0; mi < 4; ++mi) {
        #pragma unroll
        for (int ni = 0; ni < 4; ++ni) {
            const int m = m0 + wm + mi * 16 + q;
            const int n = n0 + wn + ni * 8 + 2 * t;
            float v0 = acc[mi][ni][0], v1 = acc[mi][ni][1];
            float v2 = acc[mi][ni][2], v3 = acc[mi][ni][3];
            if (ROUND_OUT) {
                v0 = __uint_as_float(f2tf(v0));
                v1 = __uint_as_float(f2tf(v1));
                v2 = __uint_as_float(f2tf(v2));
                v3 = __uint_as_float(f2tf(v3));
            }
            *(float2*)(C + (size_t)m * NCOLS + n)       = make_float2(v0, v1);
            *(float2*)(C + (size_t)(m + 8) * NCOLS + n) = make_float2(v2, v3);
        }
    }
}

// ---------------------------------------------------------------------------
extern "C" void kernel_launch(void* const* d_in, const int* in_sizes, int n_in,
                              void* d_out, int out_size) {
    const float* x   = (const float*)d_in[0];   // [16384, 2048]
    const float* adj = (const float*)d_in[1];   // [16384, 16384]
    const float* W   = (const float*)d_in[2];   // [2048, 512]
    float* out = (float*)d_out;                 // [16384, 512]

    float* h;
    cudaGetSymbolAddress((void**)&h, g_h);

    cudaFuncSetAttribute(gemm_tf32_kernel<true, true, true>,
                         cudaFuncAttributeMaxDynamicSharedMemorySize, SMEM_BYTES);
    cudaFuncSetAttribute(gemm_tf32_kernel<true, false, false>,
                         cudaFuncAttributeMaxDynamicSharedMemorySize, SMEM_BYTES);

    dim3 grid(NCOLS / BN, 16384 / BM);   // (4, 128)

    // h = round_tf32(x @ W)
    gemm_tf32_kernel<true, true, true><<<grid, NTHREADS, SMEM_BYTES>>>(
        x, W, h, 2048);
    // out = adj @ h   (h already tf32: no B cvt)
    gemm_tf32_kernel<true, false, false><<<grid, NTHREADS, SMEM_BYTES>>>(
        adj, h, out, 16384);
}

// round 6
// speedup vs baseline: 1.4481x; 1.0765x over previous
#include <cuda_runtime.h>
#include <cstdint>

// ============================================================================
// out = adj @ (x @ W)
//   x   [16384, 2048] f32  (d_in[0])
//   adj [16384,16384] f32  (d_in[1])
//   W   [ 2048,  512] f32  (d_in[2])
//   out [16384,  512] f32
//
// tf32 mma.sync GEMM. Crossbar-bound analysis => 64x64 warp tiles (4 warps,
// 128 threads, CTA 128x128) to halve smem bytes/MAC, conflict-free B stride
// (SB=136), cp.async 3-stage pipeline, frag double-buffering, 2 CTAs/SM.
// h written tf32-pre-rounded by GEMM1 so GEMM2 skips B cvt.
// ============================================================================

#define BM 128
#define BN 128
#define BK 32
#define NTHREADS 128
#define NCOLS 512
#define SA 36                  // A smem row stride (floats): 32 + 4 pad
#define SB 136                 // B smem row stride (floats): 128 + 8 pad -> bank = t*8+q, conflict-free
#define NSTAGE 3

static constexpr int A_STAGE_F   = BM * SA;                 // 4608 floats
static constexpr int B_STAGE_F   = BK * SB;                 // 4352 floats
static constexpr int STAGE_F     = A_STAGE_F + B_STAGE_F;   // 8960 floats
static constexpr int SMEM_BYTES  = NSTAGE * STAGE_F * 4;    // 107520 B (x2 CTA = 215K <= 228K)

__device__ float g_h[(size_t)16384 * NCOLS];                // 32 MB scratch

__device__ __forceinline__ uint32_t f2tf(float f) {
    uint32_t u;
    asm("cvt.rna.tf32.f32 %0, %1;" : "=r"(u) : "f"(f));
    return u;
}
__device__ __forceinline__ uint32_t f2tf_u(uint32_t x) {
    return f2tf(__uint_as_float(x));
}

__device__ __forceinline__ uint32_t smem_u32(const void* p) {
    uint32_t a;
    asm("{ .reg .u64 t; cvta.to.shared.u64 t, %1; cvt.u32.u64 %0, t; }"
        : "=r"(a) : "l"(p));
    return a;
}

__device__ __forceinline__ void cp_async16(uint32_t dst, const void* src) {
    asm volatile("cp.async.cg.shared.global [%0], [%1], 16;"
                 :: "r"(dst), "l"(src));
}
__device__ __forceinline__ void cp_commit() {
    asm volatile("cp.async.commit_group;");
}
template <int N>
__device__ __forceinline__ void cp_wait() {
    asm volatile("cp.async.wait_group %0;" :: "n"(N));
}

__device__ __forceinline__ void ldsm_x4(uint32_t* r, uint32_t addr) {
    asm volatile(
        "ldmatrix.sync.aligned.m8n8.x4.shared.b16 {%0,%1,%2,%3}, [%4];"
        : "=r"(r[0]), "=r"(r[1]), "=r"(r[2]), "=r"(r[3]) : "r"(addr));
}

__device__ __forceinline__ void mma_tf32(float* d,
                                         const uint32_t* a,
                                         const uint32_t* b) {
    asm volatile(
        "mma.sync.aligned.m16n8k8.row.col.f32.tf32.tf32.f32 "
        "{%0,%1,%2,%3}, {%4,%5,%6,%7}, {%8,%9}, {%0,%1,%2,%3};"
        : "+f"(d[0]), "+f"(d[1]), "+f"(d[2]), "+f"(d[3])
        : "r"(a[0]), "r"(a[1]), "r"(a[2]), "r"(a[3]),
          "r"(b[0]), "r"(b[1]));
}

template <bool CVT_A, bool CVT_B, bool ROUND_OUT>
__global__ void __launch_bounds__(NTHREADS, 2)
gemm_tf32_kernel(const float* __restrict__ A, const float* __restrict__ B,
                 float* __restrict__ C, int K) {
    extern __shared__ float smem[];

    const int tid  = threadIdx.x;
    const int wid  = tid >> 5;           // 0..3
    const int lane = tid & 31;
    const int q    = lane >> 2;          // 0..7
    const int t    = lane & 3;           // 0..3

    const int m0 = blockIdx.y * BM;
    const int n0 = blockIdx.x * BN;
    const int wm = (wid & 1) * 64;       // 2x2 warp grid, 64x64 warp tiles
    const int wn = (wid >> 1) * 64;

    // cp.async fill (128 threads): A 8 chunks/thread, B 8 chunks/thread
    const float* a_src = A + (size_t)(m0 + (tid >> 3)) * K + (tid & 7) * 4;
    const float* b_src = B + (size_t)(tid >> 5) * NCOLS + n0 + (tid & 31) * 4;
    const uint32_t smem_base = smem_u32(smem);
    const uint32_t a_dst = smem_base + ((tid >> 3) * SA + (tid & 7) * 4) * 4;
    const uint32_t b_dst = smem_base + (A_STAGE_F + (tid >> 5) * SB + (tid & 31) * 4) * 4;

    const int niter = K / BK;

    auto issue = [&](int sbuf, int kb) {
        const uint32_t soff = (uint32_t)(sbuf * STAGE_F * 4);
        const float* as = a_src + (size_t)kb * BK;
        const float* bs = b_src + (size_t)kb * BK * NCOLS;
        #pragma unroll
        for (int i = 0; i < 8; ++i)
            cp_async16(a_dst + soff + i * (16 * SA * 4), as + (size_t)i * 16 * K);
        #pragma unroll
        for (int i = 0; i < 8; ++i)
            cp_async16(b_dst + soff + i * (4 * SB * 4), bs + (size_t)i * 4 * NCOLS);
    };

    float acc[4][8][4];
    #pragma unroll
    for (int i = 0; i < 4; ++i)
        #pragma unroll
        for (int j = 0; j < 8; ++j)
            #pragma unroll
            for (int r = 0; r < 4; ++r)
                acc[i][j][r] = 0.0f;

    issue(0, 0); cp_commit();
    issue(1, 1); cp_commit();

    // ldmatrix lane addressing (byte offsets within a stage):
    //   row = wm + mi*16 + (lane & 15), col4 = (lane>>4)*4, +k8*8 floats
    const uint32_t a_lds = smem_base +
        (((wm + (lane & 15)) * SA + (lane >> 4) * 4) * 4);
    const int boff = A_STAGE_F + t * SB + wn + q;

    // double-buffered fragments
    uint32_t af[2][4][4];
    uint32_t bf[2][8][2];

    int buf = 0;
    for (int it = 0; it < niter; ++it) {
        cp_wait<1>();
        __syncthreads();

        // next stage's global loads first (fire-and-forget)
        if (it + 2 < niter) {
            int nb = buf + 2; if (nb >= NSTAGE) nb -= NSTAGE;
            issue(nb, it + 2);
        }
        cp_commit();

        const uint32_t a_stage = a_lds + (uint32_t)(buf * STAGE_F * 4);
        const float*   Bc      = smem + buf * STAGE_F;

        auto load_frags = [&](int k, int pb) {
            #pragma unroll
            for (int mi = 0; mi < 4; ++mi) {
                ldsm_x4(af[pb][mi], a_stage + (uint32_t)((mi * 16 * SA + k * 8) * 4));
                if (CVT_A) {
                    af[pb][mi][0] = f2tf_u(af[pb][mi][0]);
                    af[pb][mi][1] = f2tf_u(af[pb][mi][1]);
                    af[pb][mi][2] = f2tf_u(af[pb][mi][2]);
                    af[pb][mi][3] = f2tf_u(af[pb][mi][3]);
                }
            }
            #pragma unroll
            for (int ni = 0; ni < 8; ++ni) {
                const float* bb = Bc + boff + k * (8 * SB) + ni * 8;
                if (CVT_B) {
                    bf[pb][ni][0] = f2tf(bb[0]);
                    bf[pb][ni][1] = f2tf(bb[4 * SB]);
                } else {
                    bf[pb][ni][0] = ((const uint32_t*)bb)[0];
                    bf[pb][ni][1] = ((const uint32_t*)bb)[4 * SB];
                }
            }
        };

        load_frags(0, 0);

        #pragma unroll
        for (int k8 = 0; k8 < 4; ++k8) {
            const int cur = k8 & 1;
            if (k8 < 3) load_frags(k8 + 1, cur ^ 1);
            #pragma unroll
            for (int mi = 0; mi < 4; ++mi)
                #pragma unroll
                for (int ni = 0; ni < 8; ++ni)
                    mma_tf32(acc[mi][ni], af[cur][mi], bf[cur][ni]);
        }

        if (++buf >= NSTAGE) buf = 0;
    }

    // ---- epilogue ----
    #pragma unroll
    for (int mi = 0; mi < 4; ++mi) {
        #pragma unroll
        for (int ni = 0; ni < 8; ++ni) {
            const int m = m0 + wm + mi * 16 + q;
            const int n = n0 + wn + ni * 8 + 2 * t;
            float v0 = acc[mi][ni][0], v1 = acc[mi][ni][1];
            float v2 = acc[mi][ni][2], v3 = acc[mi][ni][3];
            if (ROUND_OUT) {
                v0 = __uint_as_float(f2tf(v0));
                v1 = __uint_as_float(f2tf(v1));
                v2 = __uint_as_float(f2tf(v2));
                v3 = __uint_as_float(f2tf(v3));
            }
            *(float2*)(C + (size_t)m * NCOLS + n)       = make_float2(v0, v1);
            *(float2*)(C + (size_t)(m + 8) * NCOLS + n) = make_float2(v2, v3);
        }
    }
}

// ---------------------------------------------------------------------------
extern "C" void kernel_launch(void* const* d_in, const int* in_sizes, int n_in,
                              void* d_out, int out_size) {
    const float* x   = (const float*)d_in[0];   // [16384, 2048]
    const float* adj = (const float*)d_in[1];   // [16384, 16384]
    const float* W   = (const float*)d_in[2];   // [2048, 512]
    float* out = (float*)d_out;                 // [16384, 512]

    float* h;
    cudaGetSymbolAddress((void**)&h, g_h);

    cudaFuncSetAttribute(gemm_tf32_kernel<true, true, true>,
                         cudaFuncAttributeMaxDynamicSharedMemorySize, SMEM_BYTES);
    cudaFuncSetAttribute(gemm_tf32_kernel<true, false, false>,
                         cudaFuncAttributeMaxDynamicSharedMemorySize, SMEM_BYTES);

    dim3 grid(NCOLS / BN, 16384 / BM);   // (4, 128)

    // h = round_tf32(x @ W)
    gemm_tf32_kernel<true, true, true><<<grid, NTHREADS, SMEM_BYTES>>>(
        x, W, h, 2048);
    // out = adj @ h   (h already tf32: no B cvt)
    gemm_tf32_kernel<true, false, false><<<grid, NTHREADS, SMEM_BYTES>>>(
        adj, h, out, 16384);
}